// round 16
// baseline (speedup 1.0000x reference)
#include <cuda_runtime.h>
#include <cuda_fp16.h>
#include <cstdint>
#include <math.h>

// B=128, NQ=NK=64, D_IN=1024, H=16, DK=DV=64, E=1024, D_OUT=1024
#define OUT_ELEMS (128 * 64 * 1024)

// Scratch (allocation-free)
__device__ float g_qp[128 * 64 * 1024];
__device__ float g_kp[128 * 64 * 1024];
__device__ float g_vp[128 * 64 * 1024];
__device__ float g_ctx[128 * 64 * 1024];

__device__ __forceinline__ uint32_t f2h2(float x, float y) {
    __half2 h = __float22half2_rn(make_float2(x, y));
    return *(uint32_t*)&h;
}

__device__ __forceinline__ uint32_t smem_u32(const void* p) {
    uint32_t a;
    asm("{ .reg .u64 t; cvta.to.shared.u64 t, %1; cvt.u32.u64 %0, t; }"
        : "=r"(a) : "l"(p));
    return a;
}

// D += A*B  (m16n8k16 fp16 in, fp32 acc, row.col)
__device__ __forceinline__ void mma16(float* d, const uint32_t* a, const uint32_t* b) {
    asm volatile(
        "mma.sync.aligned.m16n8k16.row.col.f32.f16.f16.f32 "
        "{%0,%1,%2,%3},{%4,%5,%6,%7},{%8,%9},{%0,%1,%2,%3};"
        : "+f"(d[0]), "+f"(d[1]), "+f"(d[2]), "+f"(d[3])
        : "r"(a[0]), "r"(a[1]), "r"(a[2]), "r"(a[3]), "r"(b[0]), "r"(b[1]));
}

__device__ __forceinline__ void lm_x4_trans(uint32_t addr, uint32_t* r) {
    asm volatile("ldmatrix.sync.aligned.m8n8.x4.trans.shared.b16 {%0,%1,%2,%3}, [%4];"
                 : "=r"(r[0]), "=r"(r[1]), "=r"(r[2]), "=r"(r[3]) : "r"(addr));
}

// GEMM SMEM strides
#define HSTRIDE 40
#define BSTRIDE 136
#define A_TILE_H (128 * HSTRIDE)    // 5120 halves
#define STAGE_H (2 * A_TILE_H)      // 10240 halves per stage = 20 KB

// ---------------------------------------------------------------------------
// Grouped projections (R12 version — unchanged this round).
// ---------------------------------------------------------------------------
__global__ void __launch_bounds__(256, 2) proj_mma(
    const float* __restrict__ q,   const float* __restrict__ k,   const float* __restrict__ v,
    const float* __restrict__ w_q, const float* __restrict__ w_k, const float* __restrict__ w_v,
    float* __restrict__ qp, float* __restrict__ kp, float* __restrict__ vp)
{
    extern __shared__ __half smh[];
    const uint32_t sbu = smem_u32(smh);
    const int tid = threadIdx.x;
    const int lane = tid & 31, wid = tid >> 5;
    const int wm = wid >> 1, wn = wid & 1;
    const int g = blockIdx.y;
    const int nBase = blockIdx.x * 128;
    const int z = blockIdx.z;

    const float* X = (z == 0) ? q : (z == 1) ? k : v;
    const float* W = (z == 0) ? w_q : (z == 1) ? w_k : w_v;
    float* C = (z == 0) ? qp : (z == 1) ? kp : vp;

    const float* Xg = X + (size_t)g * 1024;
    const float* Wg = W + (size_t)g * 1048576 + nBase;

    const int kr = tid >> 3;
    const int lc = tid & 7;

    const uint32_t boff =
        (((((lane >> 3) & 1) * 8 + (lane & 7)) * BSTRIDE + wn * 64 + ((lane >> 4) & 1) * 8)) * 2;

    float acc[2][8][4] = {};
    float4 aw[4], bw[4];

#define PROJ_LDG(k0)                                                           \
    do {                                                                       \
        _Pragma("unroll") for (int p = 0; p < 4; p++) {                        \
            int r = p * 32 + (tid >> 3);                                       \
            aw[p] = *(const float4*)(Xg + (size_t)r * 65536 + (k0) + lc * 4);  \
        }                                                                      \
        _Pragma("unroll") for (int j = 0; j < 4; j++)                          \
            bw[j] = *(const float4*)(Wg + (size_t)((k0) + kr) * 1024 + j * 32 + lc * 4); \
    } while (0)

#define PROJ_STS(s)                                                            \
    do {                                                                       \
        __half* aS = smh + (s) * STAGE_H;                                      \
        __half* bS = aS + A_TILE_H;                                            \
        _Pragma("unroll") for (int p = 0; p < 4; p++) {                        \
            int r = p * 32 + (tid >> 3);                                       \
            *(uint2*)(aS + r * HSTRIDE + lc * 4) =                             \
                make_uint2(f2h2(aw[p].x, aw[p].y), f2h2(aw[p].z, aw[p].w));    \
        }                                                                      \
        _Pragma("unroll") for (int j = 0; j < 4; j++)                          \
            *(uint2*)(bS + kr * BSTRIDE + j * 32 + lc * 4) =                   \
                make_uint2(f2h2(bw[j].x, bw[j].y), f2h2(bw[j].z, bw[j].w));    \
    } while (0)

#define GEMM_COMPUTE(sbase)                                                     \
    do {                                                                        \
        const __half* aS = smh + (sbase);                                       \
        const uint32_t bB = sbu + (uint32_t)(sbase) * 2 + A_TILE_H * 2;         \
        _Pragma("unroll") for (int kk = 0; kk < 2; kk++) {                      \
            const int kcol = kk * 16 + (lane & 3) * 2;                          \
            uint32_t af[2][4], bf[8][2];                                        \
            _Pragma("unroll") for (int mt = 0; mt < 2; mt++) {                  \
                int row = wm * 32 + mt * 16 + (lane >> 2);                      \
                af[mt][0] = *(const uint32_t*)(aS + row * HSTRIDE + kcol);      \
                af[mt][1] = *(const uint32_t*)(aS + (row + 8) * HSTRIDE + kcol);\
                af[mt][2] = *(const uint32_t*)(aS + row * HSTRIDE + kcol + 8);  \
                af[mt][3] = *(const uint32_t*)(aS + (row + 8) * HSTRIDE + kcol + 8); \
            }                                                                   \
            _Pragma("unroll") for (int t = 0; t < 4; t++) {                     \
                uint32_t r[4];                                                  \
                lm_x4_trans(bB + boff + kk * (16 * BSTRIDE * 2) + t * 32, r);   \
                bf[2*t][0] = r[0]; bf[2*t][1] = r[1];                           \
                bf[2*t+1][0] = r[2]; bf[2*t+1][1] = r[3];                       \
            }                                                                   \
            _Pragma("unroll") for (int mt = 0; mt < 2; mt++)                    \
                _Pragma("unroll") for (int nt = 0; nt < 8; nt++)                \
                    mma16(acc[mt][nt], af[mt], bf[nt]);                         \
        }                                                                       \
    } while (0)

    PROJ_LDG(0);
    PROJ_STS(0);
    __syncthreads();

    for (int i = 0; i < 32; i++) {
        const int s = i & 1;
        if (i < 31) PROJ_LDG((i + 1) * 32);
        GEMM_COMPUTE(s * STAGE_H);
        if (i < 31) {
            PROJ_STS(1 - s);
            __syncthreads();
        }
    }

    float* Cg = C + (size_t)g * 1024 + nBase;
#pragma unroll
    for (int mt = 0; mt < 2; mt++) {
#pragma unroll
        for (int nt = 0; nt < 8; nt++) {
            int row = wm * 32 + mt * 16 + (lane >> 2);
            int col = wn * 64 + nt * 8 + (lane & 3) * 2;
            *(float2*)(Cg + (size_t)row * 65536 + col) =
                make_float2(acc[mt][nt][0], acc[mt][nt][1]);
            *(float2*)(Cg + (size_t)(row + 8) * 65536 + col) =
                make_float2(acc[mt][nt][2], acc[mt][nt][3]);
        }
    }
#undef PROJ_LDG
#undef PROJ_STS
#undef GEMM_COMPUTE
}

// ---------------------------------------------------------------------------
// FUSED fc + gate GEMM (R11 version — unchanged).
// ---------------------------------------------------------------------------
#define BF_OFF A_TILE_H
#define BG_OFF (A_TILE_H + 64 * HSTRIDE)

__global__ void __launch_bounds__(256, 2) fused_fc_gate(
    const float* __restrict__ A, const float* __restrict__ fcw,
    const float* __restrict__ fb, const float* __restrict__ gw,
    const float* __restrict__ gb, float* __restrict__ out)
{
    extern __shared__ __half smh[];
    const int tid = threadIdx.x;
    const int lane = tid & 31, wid = tid >> 5;
    const int wm = wid >> 1, wn = wid & 1;
    const int mBase = blockIdx.y * 128;
    const int nBase = blockIdx.x * 64;
    const int lc = tid & 7;

    float accF[2][4][4] = {};
    float accG[2][4][4] = {};
    float4 aw[4], fw[2], gwv[2];

#define FG_LDG(k0)                                                             \
    do {                                                                       \
        _Pragma("unroll") for (int p = 0; p < 4; p++) {                        \
            int r = p * 32 + (tid >> 3);                                       \
            aw[p] = *(const float4*)(A + (size_t)(mBase + r) * 1024 + (k0) + lc * 4); \
        }                                                                      \
        _Pragma("unroll") for (int p = 0; p < 2; p++) {                        \
            int r = p * 32 + (tid >> 3);                                       \
            fw[p]  = *(const float4*)(fcw + (size_t)(nBase + r) * 1024 + (k0) + lc * 4); \
            gwv[p] = *(const float4*)(gw  + (size_t)(nBase + r) * 1024 + (k0) + lc * 4); \
        }                                                                      \
    } while (0)

#define FG_STS(s)                                                              \
    do {                                                                       \
        __half* aS = smh + (s) * STAGE_H;                                      \
        __half* fS = aS + BF_OFF;                                              \
        __half* gS = aS + BG_OFF;                                              \
        _Pragma("unroll") for (int p = 0; p < 4; p++) {                        \
            int r = p * 32 + (tid >> 3);                                       \
            *(uint2*)(aS + r * HSTRIDE + lc * 4) =                             \
                make_uint2(f2h2(aw[p].x, aw[p].y), f2h2(aw[p].z, aw[p].w));    \
        }                                                                      \
        _Pragma("unroll") for (int p = 0; p < 2; p++) {                        \
            int r = p * 32 + (tid >> 3);                                       \
            *(uint2*)(fS + r * HSTRIDE + lc * 4) =                             \
                make_uint2(f2h2(fw[p].x, fw[p].y), f2h2(fw[p].z, fw[p].w));    \
            *(uint2*)(gS + r * HSTRIDE + lc * 4) =                             \
                make_uint2(f2h2(gwv[p].x, gwv[p].y), f2h2(gwv[p].z, gwv[p].w));\
        }                                                                      \
    } while (0)

#define FG_COMPUTE(sbase)                                                       \
    do {                                                                        \
        const __half* aS = smh + (sbase);                                       \
        const __half* fS = aS + BF_OFF;                                         \
        const __half* gS = aS + BG_OFF;                                         \
        _Pragma("unroll") for (int kk = 0; kk < 2; kk++) {                      \
            const int kcol = kk * 16 + (lane & 3) * 2;                          \
            uint32_t af[2][4], bfF[4][2], bfG[4][2];                            \
            _Pragma("unroll") for (int mt = 0; mt < 2; mt++) {                  \
                int row = wm * 32 + mt * 16 + (lane >> 2);                      \
                af[mt][0] = *(const uint32_t*)(aS + row * HSTRIDE + kcol);      \
                af[mt][1] = *(const uint32_t*)(aS + (row + 8) * HSTRIDE + kcol);\
                af[mt][2] = *(const uint32_t*)(aS + row * HSTRIDE + kcol + 8);  \
                af[mt][3] = *(const uint32_t*)(aS + (row + 8) * HSTRIDE + kcol + 8); \
            }                                                                   \
            _Pragma("unroll") for (int nt = 0; nt < 4; nt++) {                  \
                int n = wn * 32 + nt * 8 + (lane >> 2);                         \
                bfF[nt][0] = *(const uint32_t*)(fS + n * HSTRIDE + kcol);       \
                bfF[nt][1] = *(const uint32_t*)(fS + n * HSTRIDE + kcol + 8);   \
                bfG[nt][0] = *(const uint32_t*)(gS + n * HSTRIDE + kcol);       \
                bfG[nt][1] = *(const uint32_t*)(gS + n * HSTRIDE + kcol + 8);   \
            }                                                                   \
            _Pragma("unroll") for (int mt = 0; mt < 2; mt++)                    \
                _Pragma("unroll") for (int nt = 0; nt < 4; nt++) {              \
                    mma16(accF[mt][nt], af[mt], bfF[nt]);                       \
                    mma16(accG[mt][nt], af[mt], bfG[nt]);                       \
                }                                                               \
        }                                                                       \
    } while (0)

    FG_LDG(0);
    FG_STS(0);
    __syncthreads();

    for (int i = 0; i < 32; i++) {
        const int s = i & 1;
        if (i < 31) FG_LDG((i + 1) * 32);
        FG_COMPUTE(s * STAGE_H);
        if (i < 31) {
            FG_STS(1 - s);
            __syncthreads();
        }
    }

#pragma unroll
    for (int mt = 0; mt < 2; mt++) {
#pragma unroll
        for (int nt = 0; nt < 4; nt++) {
            int row = mBase + wm * 32 + mt * 16 + (lane >> 2);
            int col = nBase + wn * 32 + nt * 8 + (lane & 3) * 2;
            float b0 = fb[col], b1 = fb[col + 1];
            float c0 = gb[col], c1 = gb[col + 1];
#pragma unroll
            for (int h = 0; h < 2; h++) {
                int r = row + h * 8;
                float f0 = accF[mt][nt][h * 2 + 0] + b0;
                float f1 = accF[mt][nt][h * 2 + 1] + b1;
                float g0 = accG[mt][nt][h * 2 + 0] + c0;
                float g1 = accG[mt][nt][h * 2 + 1] + c1;
                float2 o = make_float2(tanhf(f0) / (1.f + __expf(-g0)),
                                       tanhf(f1) / (1.f + __expf(-g1)));
                *(float2*)(out + (size_t)r * 1024 + col) = o;
            }
        }
    }
#undef FG_LDG
#undef FG_STS
#undef FG_COMPUTE
}

// ---------------------------------------------------------------------------
// NEW: fp16-MMA attention. One CTA per (b,h), 128 threads (4 warps).
// Warp w computes query rows [16w, 16w+16).
// S = QK^T/8 (fp16 mma, fp32 acc) -> softmax in fp32 on fragments ->
// probs written to d_out from fragments -> AV with A-frags repacked in regs,
// V via ldmatrix.x4.trans from as-loaded [key][dv] tile.
// ---------------------------------------------------------------------------
#define VSTRIDE 72   // 64 + 8 halves pad

__global__ void __launch_bounds__(128) attn_mma(
    const float* __restrict__ qp, const float* __restrict__ kp,
    const float* __restrict__ vp, float* __restrict__ attn_out,
    float* __restrict__ ctx)
{
    __shared__ __half qs[64 * VSTRIDE];
    __shared__ __half ks[64 * VSTRIDE];
    __shared__ __half vs[64 * VSTRIDE];

    const int bh = blockIdx.x;
    const int b = bh >> 4;
    const int h = bh & 15;
    const int tid = threadIdx.x;
    const int lane = tid & 31, wid = tid >> 5;

    const float* qb = qp + (size_t)(b * 64) * 1024 + h * 64;
    const float* kb = kp + (size_t)(b * 64) * 1024 + h * 64;
    const float* vb = vp + (size_t)(b * 64) * 1024 + h * 64;

    // stage + convert: 64 rows x 16 float4 per tensor, 8 per thread
#pragma unroll
    for (int p = 0; p < 8; p++) {
        int idx = p * 128 + tid;
        int row = idx >> 4, c4 = idx & 15;
        float4 a = *(const float4*)(qb + (size_t)row * 1024 + c4 * 4);
        *(uint2*)(qs + row * VSTRIDE + c4 * 4) =
            make_uint2(f2h2(a.x, a.y), f2h2(a.z, a.w));
        float4 c = *(const float4*)(kb + (size_t)row * 1024 + c4 * 4);
        *(uint2*)(ks + row * VSTRIDE + c4 * 4) =
            make_uint2(f2h2(c.x, c.y), f2h2(c.z, c.w));
        float4 d = *(const float4*)(vb + (size_t)row * 1024 + c4 * 4);
        *(uint2*)(vs + row * VSTRIDE + c4 * 4) =
            make_uint2(f2h2(d.x, d.y), f2h2(d.z, d.w));
    }
    __syncthreads();

    const int r = wid * 16 + (lane >> 2);   // query row (and r+8)
    const int kcol0 = (lane & 3) * 2;

    // ---- S = Q K^T ----
    float s[8][4] = {};
#pragma unroll
    for (int kk = 0; kk < 4; kk++) {
        const int kc = kk * 16 + kcol0;
        uint32_t a[4];
        a[0] = *(const uint32_t*)(qs + r * VSTRIDE + kc);
        a[1] = *(const uint32_t*)(qs + (r + 8) * VSTRIDE + kc);
        a[2] = *(const uint32_t*)(qs + r * VSTRIDE + kc + 8);
        a[3] = *(const uint32_t*)(qs + (r + 8) * VSTRIDE + kc + 8);
#pragma unroll
        for (int nt = 0; nt < 8; nt++) {
            const int n = nt * 8 + (lane >> 2);
            uint32_t bfr[2];
            bfr[0] = *(const uint32_t*)(ks + n * VSTRIDE + kc);
            bfr[1] = *(const uint32_t*)(ks + n * VSTRIDE + kc + 8);
            mma16(s[nt], a, bfr);
        }
    }

    // ---- softmax (rows r and r+8; each spread over lanes sharing lane>>2) ----
    float m0 = -1e30f, m1 = -1e30f;
#pragma unroll
    for (int nt = 0; nt < 8; nt++) {
#pragma unroll
        for (int e = 0; e < 4; e++) s[nt][e] *= 0.125f;
        m0 = fmaxf(m0, fmaxf(s[nt][0], s[nt][1]));
        m1 = fmaxf(m1, fmaxf(s[nt][2], s[nt][3]));
    }
    m0 = fmaxf(m0, __shfl_xor_sync(0xffffffffu, m0, 1));
    m0 = fmaxf(m0, __shfl_xor_sync(0xffffffffu, m0, 2));
    m1 = fmaxf(m1, __shfl_xor_sync(0xffffffffu, m1, 1));
    m1 = fmaxf(m1, __shfl_xor_sync(0xffffffffu, m1, 2));
    float s0 = 0.f, s1 = 0.f;
#pragma unroll
    for (int nt = 0; nt < 8; nt++) {
        s[nt][0] = __expf(s[nt][0] - m0);
        s[nt][1] = __expf(s[nt][1] - m0);
        s[nt][2] = __expf(s[nt][2] - m1);
        s[nt][3] = __expf(s[nt][3] - m1);
        s0 += s[nt][0] + s[nt][1];
        s1 += s[nt][2] + s[nt][3];
    }
    s0 += __shfl_xor_sync(0xffffffffu, s0, 1);
    s0 += __shfl_xor_sync(0xffffffffu, s0, 2);
    s1 += __shfl_xor_sync(0xffffffffu, s1, 1);
    s1 += __shfl_xor_sync(0xffffffffu, s1, 2);
    const float i0 = 1.f / s0, i1 = 1.f / s1;
#pragma unroll
    for (int nt = 0; nt < 8; nt++) {
        s[nt][0] *= i0; s[nt][1] *= i0;
        s[nt][2] *= i1; s[nt][3] *= i1;
    }

    // ---- write attn probs [B,H,NQ,NK] from fragments ----
    float* aout = attn_out + (size_t)(b * 16 + h) * 4096;
#pragma unroll
    for (int nt = 0; nt < 8; nt++) {
        *(float2*)(aout + r * 64 + nt * 8 + kcol0) = make_float2(s[nt][0], s[nt][1]);
        *(float2*)(aout + (r + 8) * 64 + nt * 8 + kcol0) = make_float2(s[nt][2], s[nt][3]);
    }

    // ---- O = P V  (A-frags repacked from prob frags; V via ldmatrix.trans) ----
    const uint32_t vsu = smem_u32(vs);
    const uint32_t boff =
        ((((lane >> 3) & 1) * 8 + (lane & 7)) * VSTRIDE + ((lane >> 4) & 1) * 8) * 2;

    float o[8][4] = {};
#pragma unroll
    for (int kk = 0; kk < 4; kk++) {    // key 16-blocks
        uint32_t a[4];
        a[0] = f2h2(s[2 * kk][0], s[2 * kk][1]);
        a[1] = f2h2(s[2 * kk][2], s[2 * kk][3]);
        a[2] = f2h2(s[2 * kk + 1][0], s[2 * kk + 1][1]);
        a[3] = f2h2(s[2 * kk + 1][2], s[2 * kk + 1][3]);
#pragma unroll
        for (int t = 0; t < 4; t++) {   // dv 16-blocks
            uint32_t rr[4];
            lm_x4_trans(vsu + boff + kk * (16 * VSTRIDE * 2) + t * 32, rr);
            uint32_t b0[2] = {rr[0], rr[1]};
            uint32_t b1[2] = {rr[2], rr[3]};
            mma16(o[2 * t], a, b0);
            mma16(o[2 * t + 1], a, b1);
        }
    }

    float* cb = ctx + (size_t)(b * 64) * 1024 + h * 64;
#pragma unroll
    for (int t = 0; t < 8; t++) {
        *(float2*)(cb + (size_t)r * 1024 + t * 8 + kcol0) = make_float2(o[t][0], o[t][1]);
        *(float2*)(cb + (size_t)(r + 8) * 1024 + t * 8 + kcol0) = make_float2(o[t][2], o[t][3]);
    }
}

// ---------------------------------------------------------------------------
// Launch
// ---------------------------------------------------------------------------
extern "C" void kernel_launch(void* const* d_in, const int* in_sizes, int n_in,
                              void* d_out, int out_size) {
    const float* q    = (const float*)d_in[0];
    const float* k    = (const float*)d_in[1];
    const float* v    = (const float*)d_in[2];
    const float* w_q  = (const float*)d_in[3];
    const float* w_k  = (const float*)d_in[4];
    const float* w_v  = (const float*)d_in[5];
    const float* fc_w = (const float*)d_in[6];
    const float* fc_b = (const float*)d_in[7];
    const float* g_w  = (const float*)d_in[8];
    const float* g_b  = (const float*)d_in[9];

    float* out = (float*)d_out;
    float* attn = (float*)d_out + OUT_ELEMS;

    float *qp, *kp, *vp, *ctx;
    cudaGetSymbolAddress((void**)&qp, g_qp);
    cudaGetSymbolAddress((void**)&kp, g_kp);
    cudaGetSymbolAddress((void**)&vp, g_vp);
    cudaGetSymbolAddress((void**)&ctx, g_ctx);

    const int SMEM = 2 * STAGE_H * 2;  // 40960 B
    cudaFuncSetAttribute(proj_mma, cudaFuncAttributeMaxDynamicSharedMemorySize, SMEM);
    cudaFuncSetAttribute(fused_fc_gate, cudaFuncAttributeMaxDynamicSharedMemorySize, SMEM);

    dim3 gp(8, 64, 3);
    proj_mma<<<gp, 256, SMEM>>>(q, k, v, w_q, w_k, w_v, qp, kp, vp);

    attn_mma<<<2048, 128>>>(qp, kp, vp, attn, ctx);

    dim3 gf(16, 64);
    fused_fc_gate<<<gf, 256, SMEM>>>(ctx, fc_w, fc_b, g_w, g_b, out);
}

// round 17
// speedup vs baseline: 1.0047x; 1.0047x over previous
#include <cuda_runtime.h>
#include <cuda_fp16.h>
#include <cstdint>
#include <math.h>

// B=128, NQ=NK=64, D_IN=1024, H=16, DK=DV=64, E=1024, D_OUT=1024
#define OUT_ELEMS (128 * 64 * 1024)

// Scratch (allocation-free)
__device__ float g_qp[128 * 64 * 1024];
__device__ float g_kp[128 * 64 * 1024];
__device__ float g_vp[128 * 64 * 1024];
__device__ float g_ctx[128 * 64 * 1024];

__device__ __forceinline__ uint32_t f2h2(float x, float y) {
    __half2 h = __float22half2_rn(make_float2(x, y));
    return *(uint32_t*)&h;
}

__device__ __forceinline__ uint32_t smem_u32(const void* p) {
    uint32_t a;
    asm("{ .reg .u64 t; cvta.to.shared.u64 t, %1; cvt.u32.u64 %0, t; }"
        : "=r"(a) : "l"(p));
    return a;
}

// D += A*B  (m16n8k16 fp16 in, fp32 acc, row.col)
__device__ __forceinline__ void mma16(float* d, const uint32_t* a, const uint32_t* b) {
    asm volatile(
        "mma.sync.aligned.m16n8k16.row.col.f32.f16.f16.f32 "
        "{%0,%1,%2,%3},{%4,%5,%6,%7},{%8,%9},{%0,%1,%2,%3};"
        : "+f"(d[0]), "+f"(d[1]), "+f"(d[2]), "+f"(d[3])
        : "r"(a[0]), "r"(a[1]), "r"(a[2]), "r"(a[3]), "r"(b[0]), "r"(b[1]));
}

__device__ __forceinline__ void lm_x4_trans(uint32_t addr, uint32_t* r) {
    asm volatile("ldmatrix.sync.aligned.m8n8.x4.trans.shared.b16 {%0,%1,%2,%3}, [%4];"
                 : "=r"(r[0]), "=r"(r[1]), "=r"(r[2]), "=r"(r[3]) : "r"(addr));
}

// GEMM SMEM strides
#define HSTRIDE 40
#define BSTRIDE 136
#define A_TILE_H (128 * HSTRIDE)    // 5120 halves
#define STAGE_H (2 * A_TILE_H)      // 10240 halves per stage = 20 KB

// ---------------------------------------------------------------------------
// Grouped projections (R12 version — unchanged this round).
// ---------------------------------------------------------------------------
__global__ void __launch_bounds__(256, 2) proj_mma(
    const float* __restrict__ q,   const float* __restrict__ k,   const float* __restrict__ v,
    const float* __restrict__ w_q, const float* __restrict__ w_k, const float* __restrict__ w_v,
    float* __restrict__ qp, float* __restrict__ kp, float* __restrict__ vp)
{
    extern __shared__ __half smh[];
    const uint32_t sbu = smem_u32(smh);
    const int tid = threadIdx.x;
    const int lane = tid & 31, wid = tid >> 5;
    const int wm = wid >> 1, wn = wid & 1;
    const int g = blockIdx.y;
    const int nBase = blockIdx.x * 128;
    const int z = blockIdx.z;

    const float* X = (z == 0) ? q : (z == 1) ? k : v;
    const float* W = (z == 0) ? w_q : (z == 1) ? w_k : w_v;
    float* C = (z == 0) ? qp : (z == 1) ? kp : vp;

    const float* Xg = X + (size_t)g * 1024;
    const float* Wg = W + (size_t)g * 1048576 + nBase;

    const int kr = tid >> 3;
    const int lc = tid & 7;

    const uint32_t boff =
        (((((lane >> 3) & 1) * 8 + (lane & 7)) * BSTRIDE + wn * 64 + ((lane >> 4) & 1) * 8)) * 2;

    float acc[2][8][4] = {};
    float4 aw[4], bw[4];

#define PROJ_LDG(k0)                                                           \
    do {                                                                       \
        _Pragma("unroll") for (int p = 0; p < 4; p++) {                        \
            int r = p * 32 + (tid >> 3);                                       \
            aw[p] = *(const float4*)(Xg + (size_t)r * 65536 + (k0) + lc * 4);  \
        }                                                                      \
        _Pragma("unroll") for (int j = 0; j < 4; j++)                          \
            bw[j] = *(const float4*)(Wg + (size_t)((k0) + kr) * 1024 + j * 32 + lc * 4); \
    } while (0)

#define PROJ_STS(s)                                                            \
    do {                                                                       \
        __half* aS = smh + (s) * STAGE_H;                                      \
        __half* bS = aS + A_TILE_H;                                            \
        _Pragma("unroll") for (int p = 0; p < 4; p++) {                        \
            int r = p * 32 + (tid >> 3);                                       \
            *(uint2*)(aS + r * HSTRIDE + lc * 4) =                             \
                make_uint2(f2h2(aw[p].x, aw[p].y), f2h2(aw[p].z, aw[p].w));    \
        }                                                                      \
        _Pragma("unroll") for (int j = 0; j < 4; j++)                          \
            *(uint2*)(bS + kr * BSTRIDE + j * 32 + lc * 4) =                   \
                make_uint2(f2h2(bw[j].x, bw[j].y), f2h2(bw[j].z, bw[j].w));    \
    } while (0)

#define GEMM_COMPUTE(sbase)                                                     \
    do {                                                                        \
        const __half* aS = smh + (sbase);                                       \
        const uint32_t bB = sbu + (uint32_t)(sbase) * 2 + A_TILE_H * 2;         \
        _Pragma("unroll") for (int kk = 0; kk < 2; kk++) {                      \
            const int kcol = kk * 16 + (lane & 3) * 2;                          \
            uint32_t af[2][4], bf[8][2];                                        \
            _Pragma("unroll") for (int mt = 0; mt < 2; mt++) {                  \
                int row = wm * 32 + mt * 16 + (lane >> 2);                      \
                af[mt][0] = *(const uint32_t*)(aS + row * HSTRIDE + kcol);      \
                af[mt][1] = *(const uint32_t*)(aS + (row + 8) * HSTRIDE + kcol);\
                af[mt][2] = *(const uint32_t*)(aS + row * HSTRIDE + kcol + 8);  \
                af[mt][3] = *(const uint32_t*)(aS + (row + 8) * HSTRIDE + kcol + 8); \
            }                                                                   \
            _Pragma("unroll") for (int t = 0; t < 4; t++) {                     \
                uint32_t r[4];                                                  \
                lm_x4_trans(bB + boff + kk * (16 * BSTRIDE * 2) + t * 32, r);   \
                bf[2*t][0] = r[0]; bf[2*t][1] = r[1];                           \
                bf[2*t+1][0] = r[2]; bf[2*t+1][1] = r[3];                       \
            }                                                                   \
            _Pragma("unroll") for (int mt = 0; mt < 2; mt++)                    \
                _Pragma("unroll") for (int nt = 0; nt < 8; nt++)                \
                    mma16(acc[mt][nt], af[mt], bf[nt]);                         \
        }                                                                       \
    } while (0)

    PROJ_LDG(0);
    PROJ_STS(0);
    __syncthreads();

    for (int i = 0; i < 32; i++) {
        const int s = i & 1;
        if (i < 31) PROJ_LDG((i + 1) * 32);
        GEMM_COMPUTE(s * STAGE_H);
        if (i < 31) {
            PROJ_STS(1 - s);
            __syncthreads();
        }
    }

    float* Cg = C + (size_t)g * 1024 + nBase;
#pragma unroll
    for (int mt = 0; mt < 2; mt++) {
#pragma unroll
        for (int nt = 0; nt < 8; nt++) {
            int row = wm * 32 + mt * 16 + (lane >> 2);
            int col = wn * 64 + nt * 8 + (lane & 3) * 2;
            *(float2*)(Cg + (size_t)row * 65536 + col) =
                make_float2(acc[mt][nt][0], acc[mt][nt][1]);
            *(float2*)(Cg + (size_t)(row + 8) * 65536 + col) =
                make_float2(acc[mt][nt][2], acc[mt][nt][3]);
        }
    }
#undef PROJ_LDG
#undef PROJ_STS
#undef GEMM_COMPUTE
}

// ---------------------------------------------------------------------------
// FUSED fc + gate GEMM (R11 version — unchanged).
// ---------------------------------------------------------------------------
#define BF_OFF A_TILE_H
#define BG_OFF (A_TILE_H + 64 * HSTRIDE)

__global__ void __launch_bounds__(256, 2) fused_fc_gate(
    const float* __restrict__ A, const float* __restrict__ fcw,
    const float* __restrict__ fb, const float* __restrict__ gw,
    const float* __restrict__ gb, float* __restrict__ out)
{
    extern __shared__ __half smh[];
    const int tid = threadIdx.x;
    const int lane = tid & 31, wid = tid >> 5;
    const int wm = wid >> 1, wn = wid & 1;
    const int mBase = blockIdx.y * 128;
    const int nBase = blockIdx.x * 64;
    const int lc = tid & 7;

    float accF[2][4][4] = {};
    float accG[2][4][4] = {};
    float4 aw[4], fw[2], gwv[2];

#define FG_LDG(k0)                                                             \
    do {                                                                       \
        _Pragma("unroll") for (int p = 0; p < 4; p++) {                        \
            int r = p * 32 + (tid >> 3);                                       \
            aw[p] = *(const float4*)(A + (size_t)(mBase + r) * 1024 + (k0) + lc * 4); \
        }                                                                      \
        _Pragma("unroll") for (int p = 0; p < 2; p++) {                        \
            int r = p * 32 + (tid >> 3);                                       \
            fw[p]  = *(const float4*)(fcw + (size_t)(nBase + r) * 1024 + (k0) + lc * 4); \
            gwv[p] = *(const float4*)(gw  + (size_t)(nBase + r) * 1024 + (k0) + lc * 4); \
        }                                                                      \
    } while (0)

#define FG_STS(s)                                                              \
    do {                                                                       \
        __half* aS = smh + (s) * STAGE_H;                                      \
        __half* fS = aS + BF_OFF;                                              \
        __half* gS = aS + BG_OFF;                                              \
        _Pragma("unroll") for (int p = 0; p < 4; p++) {                        \
            int r = p * 32 + (tid >> 3);                                       \
            *(uint2*)(aS + r * HSTRIDE + lc * 4) =                             \
                make_uint2(f2h2(aw[p].x, aw[p].y), f2h2(aw[p].z, aw[p].w));    \
        }                                                                      \
        _Pragma("unroll") for (int p = 0; p < 2; p++) {                        \
            int r = p * 32 + (tid >> 3);                                       \
            *(uint2*)(fS + r * HSTRIDE + lc * 4) =                             \
                make_uint2(f2h2(fw[p].x, fw[p].y), f2h2(fw[p].z, fw[p].w));    \
            *(uint2*)(gS + r * HSTRIDE + lc * 4) =                             \
                make_uint2(f2h2(gwv[p].x, gwv[p].y), f2h2(gwv[p].z, gwv[p].w));\
        }                                                                      \
    } while (0)

#define FG_COMPUTE(sbase)                                                       \
    do {                                                                        \
        const __half* aS = smh + (sbase);                                       \
        const __half* fS = aS + BF_OFF;                                         \
        const __half* gS = aS + BG_OFF;                                         \
        _Pragma("unroll") for (int kk = 0; kk < 2; kk++) {                      \
            const int kcol = kk * 16 + (lane & 3) * 2;                          \
            uint32_t af[2][4], bfF[4][2], bfG[4][2];                            \
            _Pragma("unroll") for (int mt = 0; mt < 2; mt++) {                  \
                int row = wm * 32 + mt * 16 + (lane >> 2);                      \
                af[mt][0] = *(const uint32_t*)(aS + row * HSTRIDE + kcol);      \
                af[mt][1] = *(const uint32_t*)(aS + (row + 8) * HSTRIDE + kcol);\
                af[mt][2] = *(const uint32_t*)(aS + row * HSTRIDE + kcol + 8);  \
                af[mt][3] = *(const uint32_t*)(aS + (row + 8) * HSTRIDE + kcol + 8); \
            }                                                                   \
            _Pragma("unroll") for (int nt = 0; nt < 4; nt++) {                  \
                int n = wn * 32 + nt * 8 + (lane >> 2);                         \
                bfF[nt][0] = *(const uint32_t*)(fS + n * HSTRIDE + kcol);       \
                bfF[nt][1] = *(const uint32_t*)(fS + n * HSTRIDE + kcol + 8);   \
                bfG[nt][0] = *(const uint32_t*)(gS + n * HSTRIDE + kcol);       \
                bfG[nt][1] = *(const uint32_t*)(gS + n * HSTRIDE + kcol + 8);   \
            }                                                                   \
            _Pragma("unroll") for (int mt = 0; mt < 2; mt++)                    \
                _Pragma("unroll") for (int nt = 0; nt < 4; nt++) {              \
                    mma16(accF[mt][nt], af[mt], bfF[nt]);                       \
                    mma16(accG[mt][nt], af[mt], bfG[nt]);                       \
                }                                                               \
        }                                                                       \
    } while (0)

    FG_LDG(0);
    FG_STS(0);
    __syncthreads();

    for (int i = 0; i < 32; i++) {
        const int s = i & 1;
        if (i < 31) FG_LDG((i + 1) * 32);
        FG_COMPUTE(s * STAGE_H);
        if (i < 31) {
            FG_STS(1 - s);
            __syncthreads();
        }
    }

#pragma unroll
    for (int mt = 0; mt < 2; mt++) {
#pragma unroll
        for (int nt = 0; nt < 4; nt++) {
            int row = mBase + wm * 32 + mt * 16 + (lane >> 2);
            int col = nBase + wn * 32 + nt * 8 + (lane & 3) * 2;
            float b0 = fb[col], b1 = fb[col + 1];
            float c0 = gb[col], c1 = gb[col + 1];
#pragma unroll
            for (int h = 0; h < 2; h++) {
                int r = row + h * 8;
                float f0 = accF[mt][nt][h * 2 + 0] + b0;
                float f1 = accF[mt][nt][h * 2 + 1] + b1;
                float g0 = accG[mt][nt][h * 2 + 0] + c0;
                float g1 = accG[mt][nt][h * 2 + 1] + c1;
                float2 o = make_float2(tanhf(f0) / (1.f + __expf(-g0)),
                                       tanhf(f1) / (1.f + __expf(-g1)));
                *(float2*)(out + (size_t)r * 1024 + col) = o;
            }
        }
    }
#undef FG_LDG
#undef FG_STS
#undef FG_COMPUTE
}

// ---------------------------------------------------------------------------
// NEW: fp16-MMA attention. One CTA per (b,h), 128 threads (4 warps).
// Warp w computes query rows [16w, 16w+16).
// S = QK^T/8 (fp16 mma, fp32 acc) -> softmax in fp32 on fragments ->
// probs written to d_out from fragments -> AV with A-frags repacked in regs,
// V via ldmatrix.x4.trans from as-loaded [key][dv] tile.
// ---------------------------------------------------------------------------
#define VSTRIDE 72   // 64 + 8 halves pad

__global__ void __launch_bounds__(128) attn_mma(
    const float* __restrict__ qp, const float* __restrict__ kp,
    const float* __restrict__ vp, float* __restrict__ attn_out,
    float* __restrict__ ctx)
{
    __shared__ __half qs[64 * VSTRIDE];
    __shared__ __half ks[64 * VSTRIDE];
    __shared__ __half vs[64 * VSTRIDE];

    const int bh = blockIdx.x;
    const int b = bh >> 4;
    const int h = bh & 15;
    const int tid = threadIdx.x;
    const int lane = tid & 31, wid = tid >> 5;

    const float* qb = qp + (size_t)(b * 64) * 1024 + h * 64;
    const float* kb = kp + (size_t)(b * 64) * 1024 + h * 64;
    const float* vb = vp + (size_t)(b * 64) * 1024 + h * 64;

    // stage + convert: 64 rows x 16 float4 per tensor, 8 per thread
#pragma unroll
    for (int p = 0; p < 8; p++) {
        int idx = p * 128 + tid;
        int row = idx >> 4, c4 = idx & 15;
        float4 a = *(const float4*)(qb + (size_t)row * 1024 + c4 * 4);
        *(uint2*)(qs + row * VSTRIDE + c4 * 4) =
            make_uint2(f2h2(a.x, a.y), f2h2(a.z, a.w));
        float4 c = *(const float4*)(kb + (size_t)row * 1024 + c4 * 4);
        *(uint2*)(ks + row * VSTRIDE + c4 * 4) =
            make_uint2(f2h2(c.x, c.y), f2h2(c.z, c.w));
        float4 d = *(const float4*)(vb + (size_t)row * 1024 + c4 * 4);
        *(uint2*)(vs + row * VSTRIDE + c4 * 4) =
            make_uint2(f2h2(d.x, d.y), f2h2(d.z, d.w));
    }
    __syncthreads();

    const int r = wid * 16 + (lane >> 2);   // query row (and r+8)
    const int kcol0 = (lane & 3) * 2;

    // ---- S = Q K^T ----
    float s[8][4] = {};
#pragma unroll
    for (int kk = 0; kk < 4; kk++) {
        const int kc = kk * 16 + kcol0;
        uint32_t a[4];
        a[0] = *(const uint32_t*)(qs + r * VSTRIDE + kc);
        a[1] = *(const uint32_t*)(qs + (r + 8) * VSTRIDE + kc);
        a[2] = *(const uint32_t*)(qs + r * VSTRIDE + kc + 8);
        a[3] = *(const uint32_t*)(qs + (r + 8) * VSTRIDE + kc + 8);
#pragma unroll
        for (int nt = 0; nt < 8; nt++) {
            const int n = nt * 8 + (lane >> 2);
            uint32_t bfr[2];
            bfr[0] = *(const uint32_t*)(ks + n * VSTRIDE + kc);
            bfr[1] = *(const uint32_t*)(ks + n * VSTRIDE + kc + 8);
            mma16(s[nt], a, bfr);
        }
    }

    // ---- softmax (rows r and r+8; each spread over lanes sharing lane>>2) ----
    float m0 = -1e30f, m1 = -1e30f;
#pragma unroll
    for (int nt = 0; nt < 8; nt++) {
#pragma unroll
        for (int e = 0; e < 4; e++) s[nt][e] *= 0.125f;
        m0 = fmaxf(m0, fmaxf(s[nt][0], s[nt][1]));
        m1 = fmaxf(m1, fmaxf(s[nt][2], s[nt][3]));
    }
    m0 = fmaxf(m0, __shfl_xor_sync(0xffffffffu, m0, 1));
    m0 = fmaxf(m0, __shfl_xor_sync(0xffffffffu, m0, 2));
    m1 = fmaxf(m1, __shfl_xor_sync(0xffffffffu, m1, 1));
    m1 = fmaxf(m1, __shfl_xor_sync(0xffffffffu, m1, 2));
    float s0 = 0.f, s1 = 0.f;
#pragma unroll
    for (int nt = 0; nt < 8; nt++) {
        s[nt][0] = __expf(s[nt][0] - m0);
        s[nt][1] = __expf(s[nt][1] - m0);
        s[nt][2] = __expf(s[nt][2] - m1);
        s[nt][3] = __expf(s[nt][3] - m1);
        s0 += s[nt][0] + s[nt][1];
        s1 += s[nt][2] + s[nt][3];
    }
    s0 += __shfl_xor_sync(0xffffffffu, s0, 1);
    s0 += __shfl_xor_sync(0xffffffffu, s0, 2);
    s1 += __shfl_xor_sync(0xffffffffu, s1, 1);
    s1 += __shfl_xor_sync(0xffffffffu, s1, 2);
    const float i0 = 1.f / s0, i1 = 1.f / s1;
#pragma unroll
    for (int nt = 0; nt < 8; nt++) {
        s[nt][0] *= i0; s[nt][1] *= i0;
        s[nt][2] *= i1; s[nt][3] *= i1;
    }

    // ---- write attn probs [B,H,NQ,NK] from fragments ----
    float* aout = attn_out + (size_t)(b * 16 + h) * 4096;
#pragma unroll
    for (int nt = 0; nt < 8; nt++) {
        *(float2*)(aout + r * 64 + nt * 8 + kcol0) = make_float2(s[nt][0], s[nt][1]);
        *(float2*)(aout + (r + 8) * 64 + nt * 8 + kcol0) = make_float2(s[nt][2], s[nt][3]);
    }

    // ---- O = P V  (A-frags repacked from prob frags; V via ldmatrix.trans) ----
    const uint32_t vsu = smem_u32(vs);
    const uint32_t boff =
        ((((lane >> 3) & 1) * 8 + (lane & 7)) * VSTRIDE + ((lane >> 4) & 1) * 8) * 2;

    float o[8][4] = {};
#pragma unroll
    for (int kk = 0; kk < 4; kk++) {    // key 16-blocks
        uint32_t a[4];
        a[0] = f2h2(s[2 * kk][0], s[2 * kk][1]);
        a[1] = f2h2(s[2 * kk][2], s[2 * kk][3]);
        a[2] = f2h2(s[2 * kk + 1][0], s[2 * kk + 1][1]);
        a[3] = f2h2(s[2 * kk + 1][2], s[2 * kk + 1][3]);
#pragma unroll
        for (int t = 0; t < 4; t++) {   // dv 16-blocks
            uint32_t rr[4];
            lm_x4_trans(vsu + boff + kk * (16 * VSTRIDE * 2) + t * 32, rr);
            uint32_t b0[2] = {rr[0], rr[1]};
            uint32_t b1[2] = {rr[2], rr[3]};
            mma16(o[2 * t], a, b0);
            mma16(o[2 * t + 1], a, b1);
        }
    }

    float* cb = ctx + (size_t)(b * 64) * 1024 + h * 64;
#pragma unroll
    for (int t = 0; t < 8; t++) {
        *(float2*)(cb + (size_t)r * 1024 + t * 8 + kcol0) = make_float2(o[t][0], o[t][1]);
        *(float2*)(cb + (size_t)(r + 8) * 1024 + t * 8 + kcol0) = make_float2(o[t][2], o[t][3]);
    }
}

// ---------------------------------------------------------------------------
// Launch
// ---------------------------------------------------------------------------
extern "C" void kernel_launch(void* const* d_in, const int* in_sizes, int n_in,
                              void* d_out, int out_size) {
    const float* q    = (const float*)d_in[0];
    const float* k    = (const float*)d_in[1];
    const float* v    = (const float*)d_in[2];
    const float* w_q  = (const float*)d_in[3];
    const float* w_k  = (const float*)d_in[4];
    const float* w_v  = (const float*)d_in[5];
    const float* fc_w = (const float*)d_in[6];
    const float* fc_b = (const float*)d_in[7];
    const float* g_w  = (const float*)d_in[8];
    const float* g_b  = (const float*)d_in[9];

    float* out = (float*)d_out;
    float* attn = (float*)d_out + OUT_ELEMS;

    float *qp, *kp, *vp, *ctx;
    cudaGetSymbolAddress((void**)&qp, g_qp);
    cudaGetSymbolAddress((void**)&kp, g_kp);
    cudaGetSymbolAddress((void**)&vp, g_vp);
    cudaGetSymbolAddress((void**)&ctx, g_ctx);

    const int SMEM = 2 * STAGE_H * 2;  // 40960 B
    cudaFuncSetAttribute(proj_mma, cudaFuncAttributeMaxDynamicSharedMemorySize, SMEM);
    cudaFuncSetAttribute(fused_fc_gate, cudaFuncAttributeMaxDynamicSharedMemorySize, SMEM);

    dim3 gp(8, 64, 3);
    proj_mma<<<gp, 256, SMEM>>>(q, k, v, w_q, w_k, w_v, qp, kp, vp);

    attn_mma<<<2048, 128>>>(qp, kp, vp, attn, ctx);

    dim3 gf(16, 64);
    fused_fc_gate<<<gf, 256, SMEM>>>(ctx, fc_w, fc_b, g_w, g_b, out);
}